// round 16
// baseline (speedup 1.0000x reference)
#include <cuda_runtime.h>
#include <cuda_fp16.h>
#include <math.h>

#define D 64
#define MAXN 100000
#define MAXE 1100000

// ---------------- static device scratch ----------------
// packed per-node record: 32 x [half2(ui_c,ui_c+1) | half2(vj_c,vj_c+1)] = 256 B
__device__ unsigned g_suh[MAXN * 64];
__device__ float g_xvi[MAXN * D];
__device__ float g_y  [MAXN * D];    // stage1 output
__device__ float g_y2 [MAXN * D];    // stage2 output
__device__ float g_stats1[2 * D];
__device__ float g_stats2[2 * D];
// CSR (edges sorted by destination)
__device__ int g_cnt[MAXN + 1];
__device__ int g_off[MAXN + 1];
__device__ int g_cur[MAXN];
__device__ int g_srcSorted[MAXE];
__device__ int g_bsum[512];

// ---------------- side stream for CSR subgraph (created before harness baseline) ----------------
namespace {
struct StreamInit {
    cudaStream_t s1;
    cudaEvent_t evRoot, evCsr;
    StreamInit() {
        cudaStreamCreateWithFlags(&s1, cudaStreamNonBlocking);
        cudaEventCreateWithFlags(&evRoot, cudaEventDisableTiming);
        cudaEventCreateWithFlags(&evCsr, cudaEventDisableTiming);
    }
};
StreamInit g_si;
}

// ================= CSR build =================
__global__ void hist_kernel(const int* __restrict__ ee, int nE)
{
    int e = blockIdx.x * blockDim.x + threadIdx.x;
    if (e < nE) atomicAdd(&g_cnt[ee[e]], 1);
}

__global__ void scan_block_kernel(int n)
{
    __shared__ int sh[256];
    int tid = threadIdx.x;
    int i = blockIdx.x * 256 + tid;
    int v = (i < n) ? g_cnt[i] : 0;
    sh[tid] = v;
    __syncthreads();
    #pragma unroll
    for (int ofs = 1; ofs < 256; ofs <<= 1) {
        int x = (tid >= ofs) ? sh[tid - ofs] : 0;
        __syncthreads();
        sh[tid] += x;
        __syncthreads();
    }
    if (i < n) g_off[i] = sh[tid] - v;
    if (tid == 255) g_bsum[blockIdx.x] = sh[255];
}

__global__ void scan_add_kernel(int n)
{
    __shared__ int s_prefix;
    const int bid = blockIdx.x;
    if (bid == 0 && threadIdx.x < 128) {
        g_stats1[threadIdx.x] = 0.f;
        g_stats2[threadIdx.x] = 0.f;
    }
    if (threadIdx.x < 32) {
        int s = 0;
        for (int i = threadIdx.x; i < bid; i += 32) s += g_bsum[i];
        #pragma unroll
        for (int o = 16; o; o >>= 1) s += __shfl_down_sync(0xffffffffu, s, o);
        if (threadIdx.x == 0) s_prefix = s;
    }
    __syncthreads();
    int i = bid * 256 + threadIdx.x;
    if (i < n) {
        int o = g_off[i] + s_prefix;
        g_off[i] = o;
        g_cur[i] = o;
        if (i == n - 1) g_off[n] = o + g_cnt[i];
    }
}

__global__ void scatter_kernel(const int* __restrict__ es, const int* __restrict__ ee, int nE)
{
    int e = blockIdx.x * blockDim.x + threadIdx.x;
    if (e < nE) {
        int d = ee[e];
        int p = atomicAdd(&g_cur[d], 1);
        g_srcSorted[p] = es[e];
    }
}

// ================= tf32 mma helpers =================
__device__ __forceinline__ unsigned f2tf32(float x)
{
    unsigned r;
    asm("cvt.rna.tf32.f32 %0, %1;" : "=r"(r) : "f"(x));
    return r;
}

__device__ __forceinline__ void mma_tf32(float* d, unsigned a0, unsigned a1,
                                         unsigned a2, unsigned a3,
                                         unsigned b0, unsigned b1)
{
    asm volatile(
        "mma.sync.aligned.m16n8k8.row.col.f32.tf32.tf32.f32 "
        "{%0,%1,%2,%3}, {%4,%5,%6,%7}, {%8,%9}, {%0,%1,%2,%3};"
        : "+f"(d[0]), "+f"(d[1]), "+f"(d[2]), "+f"(d[3])
        : "r"(a0), "r"(a1), "r"(a2), "r"(a3), "r"(b0), "r"(b1));
}

__device__ __forceinline__ unsigned pack_h2(float a, float b)
{
    __half2 h = __floats2half2_rn(a, b);
    return *reinterpret_cast<unsigned*>(&h);
}

// ================= fused 4-matrix GEMM via tf32 tensor cores (persistent) =================
// W staged once per persistent block; As holds a FULL 128-row tile (one sync pair per tile).
#define WS_STRIDE 264
#define AS_STRIDE 68
#define GEMM4_SMEM ((64*WS_STRIDE + 128*AS_STRIDE)*4)

template<bool BN>
__global__ void __launch_bounds__(256, 2)
gemm4_kernel(const float* __restrict__ X, const float* __restrict__ Xv, int nU,
             const float* __restrict__ Ui, const float* __restrict__ Uj,
             const float* __restrict__ Vi, const float* __restrict__ Vj,
             const float* __restrict__ bu, const float* __restrict__ bv,
             const float* __restrict__ stats, const float* __restrict__ gamma,
             const float* __restrict__ beta,
             unsigned* __restrict__ suh, float* __restrict__ y,
             float* __restrict__ xvi,
             int n)
{
    extern __shared__ float smem[];
    unsigned* Ws = (unsigned*)smem;                       // [64][264] tf32 bits
    unsigned* As = (unsigned*)(smem + 64 * WS_STRIDE);    // [128][68] tf32 bits
    __shared__ float s_scale[64], s_shift[64];
    const int tid = threadIdx.x;

    if (BN) {
        if (tid < 64) {
            float fn = 1.f / (float)n;
            float mean = stats[tid] * fn;
            float var  = stats[64 + tid] * fn - mean * mean;
            float sc = gamma[tid] * rsqrtf(var + 1e-3f);
            s_scale[tid] = sc;
            s_shift[tid] = beta[tid] - mean * sc;
        }
        __syncthreads();
    }

    // stage W once per (persistent) block
    {
        const float* mats[4] = {Ui, Uj, Vi, Vj};
        #pragma unroll
        for (int m = 0; m < 4; m++) {
            const float4* src = (const float4*)mats[m];
            for (int i = tid; i < 1024; i += 256) {
                int k = i >> 4, j4 = i & 15;
                float4 w = src[i];
                uint4 p;
                p.x = f2tf32(w.x); p.y = f2tf32(w.y);
                p.z = f2tf32(w.z); p.w = f2tf32(w.w);
                *(uint4*)(Ws + k * WS_STRIDE + m * 64 + j4 * 4) = p;
            }
        }
    }

    const int warp = tid >> 5;
    const int lane = tid & 31;
    const int g = lane >> 2;
    const int t = lane & 3;
    const int nbase = warp * 8;
    const int c = nbase + 2 * t;
    float2 bu2 = *(const float2*)(bu + c);
    float2 bv2 = *(const float2*)(bv + c);

    const int nTiles = (n + 127) / 128;

    for (int tile = blockIdx.x; tile < nTiles; tile += gridDim.x) {
        const int rowBase0 = tile * 128;

        __syncthreads();   // protect As from previous tile's readers
        // stage full 128-row tile
        for (int i = tid; i < 2048; i += 256) {
            int r = i >> 4, c4 = i & 15;
            int row = rowBase0 + r;
            float4 v = make_float4(0.f, 0.f, 0.f, 0.f);
            if (row < n) {
                const float4* src = (row < nU) ? ((const float4*)X) + (size_t)row * 16
                                               : ((const float4*)Xv) + (size_t)(row - nU) * 16;
                v = src[c4];
            }
            if (BN) {
                int cc = c4 * 4;
                v.x = fmaxf(v.x * s_scale[cc+0] + s_shift[cc+0], 0.f);
                v.y = fmaxf(v.y * s_scale[cc+1] + s_shift[cc+1], 0.f);
                v.z = fmaxf(v.z * s_scale[cc+2] + s_shift[cc+2], 0.f);
                v.w = fmaxf(v.w * s_scale[cc+3] + s_shift[cc+3], 0.f);
            }
            uint4 p;
            p.x = f2tf32(v.x); p.y = f2tf32(v.y);
            p.z = f2tf32(v.z); p.w = f2tf32(v.w);
            *(uint4*)(As + r * AS_STRIDE + c4 * 4) = p;
        }
        __syncthreads();

        #pragma unroll 1
        for (int st = 0; st < 2; st++) {
            const int rowBase = rowBase0 + st * 64;
            if (rowBase >= n) break;
            const unsigned* Ast = As + st * 64 * AS_STRIDE;

            float acc[4][4][4];   // [mtile][matrix][c0..c3]
            #pragma unroll
            for (int mt = 0; mt < 4; mt++)
                #pragma unroll
                for (int nt = 0; nt < 4; nt++)
                    #pragma unroll
                    for (int cc = 0; cc < 4; cc++) acc[mt][nt][cc] = 0.f;

            #pragma unroll
            for (int k0 = 0; k0 < 64; k0 += 8) {
                unsigned b[4][2];
                #pragma unroll
                for (int nt = 0; nt < 4; nt++) {
                    int cb = nt * 64 + nbase;
                    b[nt][0] = Ws[(k0 + t)     * WS_STRIDE + cb + g];
                    b[nt][1] = Ws[(k0 + t + 4) * WS_STRIDE + cb + g];
                }
                #pragma unroll
                for (int mt = 0; mt < 4; mt++) {
                    int r0 = mt * 16;
                    unsigned a0 = Ast[(r0 + g)     * AS_STRIDE + k0 + t];
                    unsigned a1 = Ast[(r0 + g + 8) * AS_STRIDE + k0 + t];
                    unsigned a2 = Ast[(r0 + g)     * AS_STRIDE + k0 + t + 4];
                    unsigned a3 = Ast[(r0 + g + 8) * AS_STRIDE + k0 + t + 4];
                    #pragma unroll
                    for (int nt = 0; nt < 4; nt++)
                        mma_tf32(acc[mt][nt], a0, a1, a2, a3, b[nt][0], b[nt][1]);
                }
            }

            #pragma unroll
            for (int mt = 0; mt < 4; mt++) {
                #pragma unroll
                for (int h = 0; h < 2; h++) {
                    int row = rowBase + mt * 16 + g + 8 * h;
                    if (row < n) {
                        float u0  = acc[mt][0][2*h],   u1  = acc[mt][0][2*h+1];
                        float j0  = acc[mt][1][2*h] + bu2.x, j1 = acc[mt][1][2*h+1] + bu2.y;
                        float vi0 = acc[mt][2][2*h],   vi1 = acc[mt][2][2*h+1];
                        float vj0 = acc[mt][3][2*h] + bv2.x, vj1 = acc[mt][3][2*h+1] + bv2.y;
                        *(float2*)(y   + (size_t)row * 64 + c) = make_float2(j0, j1);
                        *(float2*)(xvi + (size_t)row * 64 + c) = make_float2(vi0, vi1);
                        uint2 pk;
                        pk.x = pack_h2(u0, u1);    // half2(ui_c, ui_c+1)
                        pk.y = pack_h2(vj0, vj1);  // half2(vj_c, vj_c+1)
                        *(uint2*)(suh + (size_t)row * 64 + c) = pk;
                    }
                }
            }
        }
    }
}

// ================= per-node aggregation: f16x2-vectorized gate, 8 nodes/warp =================
__device__ __forceinline__ __half2 u2h(unsigned u)
{
    return *reinterpret_cast<__half2*>(&u);
}

__device__ __forceinline__ __half2 tanh_h2(__half2 x)
{
    unsigned xi = *reinterpret_cast<unsigned*>(&x);
    unsigned r;
    asm("tanh.approx.f16x2 %0, %1;" : "=r"(r) : "r"(xi));
    return *reinterpret_cast<__half2*>(&r);
}

__device__ __forceinline__ void edge_acc(float4& acc, __half2 viha, __half2 vihb,
                                         __half2 h05, uint4 pk)
{
    __half2 ua = u2h(pk.x), va = u2h(pk.y);
    __half2 ub = u2h(pk.z), vb = u2h(pk.w);
    __half2 xa = __hfma2(va, h05, viha);
    __half2 xb = __hfma2(vb, h05, vihb);
    __half2 ga = __hfma2(tanh_h2(xa), h05, h05);
    __half2 gb = __hfma2(tanh_h2(xb), h05, h05);
    __half2 ma = __hmul2(ua, ga);
    __half2 mb = __hmul2(ub, gb);
    float2 fa = __half22float2(ma);
    float2 fb = __half22float2(mb);
    acc.x += fa.x; acc.y += fa.y; acc.z += fb.x; acc.w += fb.y;
}

__global__ void agg_kernel(const float* __restrict__ xvi, const unsigned* __restrict__ suh,
                           float* __restrict__ y, float* __restrict__ stats, int n)
{
    __shared__ float s_sum[64], s_sum2[64];
    const int tid = threadIdx.x;
    if (tid < 64) { s_sum[tid] = 0.f; s_sum2[tid] = 0.f; }
    __syncthreads();

    const int warp = tid >> 5;
    const int lane = tid & 31;
    const int half = lane >> 4;
    const int l4   = lane & 15;
    const int nodeBase = blockIdx.x * 64 + warp * 8;
    const __half2 h05 = __float2half2_rn(0.5f);

    float4 st1 = make_float4(0.f, 0.f, 0.f, 0.f);
    float4 st2 = make_float4(0.f, 0.f, 0.f, 0.f);

    #pragma unroll 1
    for (int q = 0; q < 8; q++) {
        const int node = nodeBase + q;
        if (node >= n) break;

        float4 vi = ((const float4*)(xvi + (size_t)node * 64))[l4];
        float4 base = ((const float4*)(y + (size_t)node * 64))[l4];
        __half2 viha = __floats2half2_rn(0.5f * vi.x, 0.5f * vi.y);
        __half2 vihb = __floats2half2_rn(0.5f * vi.z, 0.5f * vi.w);
        float4 acc = make_float4(0.f, 0.f, 0.f, 0.f);
        const int p0 = g_off[node];
        const int p1 = g_off[node + 1];

        int pp = p0 + half;
        for (; pp + 6 < p1; pp += 8) {
            int b0 = __ldg(g_srcSorted + pp);
            int b1 = __ldg(g_srcSorted + pp + 2);
            int b2 = __ldg(g_srcSorted + pp + 4);
            int b3 = __ldg(g_srcSorted + pp + 6);
            uint4 k0 = __ldg((const uint4*)(suh + (size_t)b0 * 64) + l4);
            uint4 k1 = __ldg((const uint4*)(suh + (size_t)b1 * 64) + l4);
            uint4 k2 = __ldg((const uint4*)(suh + (size_t)b2 * 64) + l4);
            uint4 k3 = __ldg((const uint4*)(suh + (size_t)b3 * 64) + l4);
            edge_acc(acc, viha, vihb, h05, k0);
            edge_acc(acc, viha, vihb, h05, k1);
            edge_acc(acc, viha, vihb, h05, k2);
            edge_acc(acc, viha, vihb, h05, k3);
        }
        for (; pp + 2 < p1; pp += 4) {
            int b0 = __ldg(g_srcSorted + pp);
            int b1 = __ldg(g_srcSorted + pp + 2);
            uint4 k0 = __ldg((const uint4*)(suh + (size_t)b0 * 64) + l4);
            uint4 k1 = __ldg((const uint4*)(suh + (size_t)b1 * 64) + l4);
            edge_acc(acc, viha, vihb, h05, k0);
            edge_acc(acc, viha, vihb, h05, k1);
        }
        for (; pp < p1; pp += 2) {
            int b = __ldg(g_srcSorted + pp);
            uint4 k = __ldg((const uint4*)(suh + (size_t)b * 64) + l4);
            edge_acc(acc, viha, vihb, h05, k);
        }

        acc.x += __shfl_xor_sync(0xffffffffu, acc.x, 16);
        acc.y += __shfl_xor_sync(0xffffffffu, acc.y, 16);
        acc.z += __shfl_xor_sync(0xffffffffu, acc.z, 16);
        acc.w += __shfl_xor_sync(0xffffffffu, acc.w, 16);

        if (half == 0) {
            acc.x += base.x; acc.y += base.y; acc.z += base.z; acc.w += base.w;
            ((float4*)(y + (size_t)node * 64))[l4] = acc;
            st1.x += acc.x; st1.y += acc.y; st1.z += acc.z; st1.w += acc.w;
            st2.x += acc.x * acc.x; st2.y += acc.y * acc.y;
            st2.z += acc.z * acc.z; st2.w += acc.w * acc.w;
        }
    }

    if (half == 0) {
        int cc = l4 * 4;
        atomicAdd(&s_sum[cc + 0], st1.x);  atomicAdd(&s_sum2[cc + 0], st2.x);
        atomicAdd(&s_sum[cc + 1], st1.y);  atomicAdd(&s_sum2[cc + 1], st2.y);
        atomicAdd(&s_sum[cc + 2], st1.z);  atomicAdd(&s_sum2[cc + 2], st2.z);
        atomicAdd(&s_sum[cc + 3], st1.w);  atomicAdd(&s_sum2[cc + 3], st2.w);
    }
    __syncthreads();
    if (tid < 64) {
        atomicAdd(stats + tid,      s_sum[tid]);
        atomicAdd(stats + 64 + tid, s_sum2[tid]);
    }
}

// ================= final: out = relu( BN2(y2) + x_in @ R ) via tf32 MMA =================
#define RS_STRIDE 72
#define FAS_STRIDE 68

__global__ void __launch_bounds__(256)
final_kernel(const float* __restrict__ Xu, const float* __restrict__ Xv, int nU,
             const float* __restrict__ R,
             const float* __restrict__ y2, const float* __restrict__ stats,
             const float* __restrict__ gamma, const float* __restrict__ beta,
             float* __restrict__ out, int n)
{
    __shared__ unsigned Rs[64 * RS_STRIDE];
    __shared__ unsigned As[64 * FAS_STRIDE];
    const int tid = threadIdx.x;
    const int rowBase = blockIdx.x * 64;

    for (int i = tid; i < 1024; i += 256) {
        int k = i >> 4, j4 = i & 15;
        float4 w = ((const float4*)R)[i];
        uint4 p;
        p.x = f2tf32(w.x); p.y = f2tf32(w.y);
        p.z = f2tf32(w.z); p.w = f2tf32(w.w);
        *(uint4*)(Rs + k * RS_STRIDE + j4 * 4) = p;
    }
    for (int i = tid; i < 1024; i += 256) {
        int r = i >> 4, c4 = i & 15;
        int row = rowBase + r;
        float4 v = make_float4(0.f, 0.f, 0.f, 0.f);
        if (row < n) {
            const float4* src = (row < nU) ? ((const float4*)Xu) + (size_t)row * 16
                                           : ((const float4*)Xv) + (size_t)(row - nU) * 16;
            v = src[c4];
        }
        uint4 p;
        p.x = f2tf32(v.x); p.y = f2tf32(v.y);
        p.z = f2tf32(v.z); p.w = f2tf32(v.w);
        *(uint4*)(As + r * FAS_STRIDE + c4 * 4) = p;
    }
    __syncthreads();

    const int warp = tid >> 5;
    const int lane = tid & 31;
    const int g = lane >> 2;
    const int t = lane & 3;
    const int cb = warp * 8;

    float acc[4][4];
    #pragma unroll
    for (int mt = 0; mt < 4; mt++)
        #pragma unroll
        for (int cc = 0; cc < 4; cc++) acc[mt][cc] = 0.f;

    #pragma unroll
    for (int k0 = 0; k0 < 64; k0 += 8) {
        unsigned b0 = Rs[(k0 + t)     * RS_STRIDE + cb + g];
        unsigned b1 = Rs[(k0 + t + 4) * RS_STRIDE + cb + g];
        #pragma unroll
        for (int mt = 0; mt < 4; mt++) {
            int r0 = mt * 16;
            unsigned a0 = As[(r0 + g)     * FAS_STRIDE + k0 + t];
            unsigned a1 = As[(r0 + g + 8) * FAS_STRIDE + k0 + t];
            unsigned a2 = As[(r0 + g)     * FAS_STRIDE + k0 + t + 4];
            unsigned a3 = As[(r0 + g + 8) * FAS_STRIDE + k0 + t + 4];
            mma_tf32(acc[mt], a0, a1, a2, a3, b0, b1);
        }
    }

    const int c = cb + 2 * t;
    float fn = 1.f / (float)n;
    float scale[2], shift[2];
    #pragma unroll
    for (int j = 0; j < 2; j++) {
        int cc = c + j;
        float mean = stats[cc] * fn;
        float var  = stats[64 + cc] * fn - mean * mean;
        float sc = gamma[cc] * rsqrtf(var + 1e-3f);
        scale[j] = sc;
        shift[j] = beta[cc] - mean * sc;
    }

    #pragma unroll
    for (int mt = 0; mt < 4; mt++) {
        #pragma unroll
        for (int h = 0; h < 2; h++) {
            int row = rowBase + mt * 16 + g + 8 * h;
            if (row < n) {
                float2 yv = *(const float2*)(y2 + (size_t)row * 64 + c);
                float o0 = acc[mt][2*h]   + yv.x * scale[0] + shift[0];
                float o1 = acc[mt][2*h+1] + yv.y * scale[1] + shift[1];
                float2 ov;
                ov.x = o0 > 0.f ? o0 : 0.f;
                ov.y = o1 > 0.f ? o1 : 0.f;
                *(float2*)(out + (size_t)row * 64 + c) = ov;
            }
        }
    }
}

// ================= host =================
extern "C" void kernel_launch(void* const* d_in, const int* in_sizes, int n_in,
                              void* d_out, int out_size)
{
    const float* u   = (const float*)d_in[0];
    const float* v   = (const float*)d_in[1];
    const int*   es  = (const int*)  d_in[2];
    const int*   ee  = (const int*)  d_in[3];
    const float* Ui1 = (const float*)d_in[4];
    const float* Uj1 = (const float*)d_in[5];
    const float* Vi1 = (const float*)d_in[6];
    const float* Vj1 = (const float*)d_in[7];
    const float* bu1 = (const float*)d_in[8];
    const float* bv1 = (const float*)d_in[9];
    const float* Ui2 = (const float*)d_in[10];
    const float* Uj2 = (const float*)d_in[11];
    const float* Vi2 = (const float*)d_in[12];
    const float* Vj2 = (const float*)d_in[13];
    const float* bu2 = (const float*)d_in[14];
    const float* bv2 = (const float*)d_in[15];
    const float* R   = (const float*)d_in[16];
    const float* gamma1 = (const float*)d_in[17];
    const float* beta1  = (const float*)d_in[18];
    const float* gamma2 = (const float*)d_in[19];
    const float* beta2  = (const float*)d_in[20];

    const int nU = in_sizes[0] / 64;
    const int nV = in_sizes[1] / 64;
    const int n  = nU + nV;
    const int nE = in_sizes[2];

    float *pxvi, *py, *py2, *pst1, *pst2;
    unsigned *psuh;
    int *pcnt;
    cudaGetSymbolAddress((void**)&psuh, g_suh);
    cudaGetSymbolAddress((void**)&pxvi, g_xvi);
    cudaGetSymbolAddress((void**)&py,   g_y);
    cudaGetSymbolAddress((void**)&py2,  g_y2);
    cudaGetSymbolAddress((void**)&pst1, g_stats1);
    cudaGetSymbolAddress((void**)&pst2, g_stats2);
    cudaGetSymbolAddress((void**)&pcnt, g_cnt);

    cudaFuncSetAttribute(gemm4_kernel<false>, cudaFuncAttributeMaxDynamicSharedMemorySize, GEMM4_SMEM);
    cudaFuncSetAttribute(gemm4_kernel<true>,  cudaFuncAttributeMaxDynamicSharedMemorySize, GEMM4_SMEM);

    const int eb = (nE + 255) / 256;
    const int nb = (n + 255) / 256;
    const int nTiles = (n + 127) / 128;
    const int gemmBlocks  = nTiles < 296 ? nTiles : 296;
    const int finalBlocks = (n + 63) / 64;
    const int aggBlocks   = (n + 63) / 64;

    cudaStream_t s1 = g_si.s1;

    // fork: CSR subgraph on side stream (depends only on es/ee)
    cudaEventRecord(g_si.evRoot, 0);
    cudaStreamWaitEvent(s1, g_si.evRoot, 0);

    cudaMemsetAsync(pcnt, 0, (MAXN + 1) * sizeof(int), s1);
    hist_kernel<<<eb, 256, 0, s1>>>(ee, nE);
    scan_block_kernel<<<nb, 256, 0, s1>>>(n);
    scan_add_kernel<<<nb, 256, 0, s1>>>(n);

    // ---- stage 1 GEMM on main stream (concurrent with CSR build) ----
    gemm4_kernel<false><<<gemmBlocks, 256, GEMM4_SMEM>>>(u, v, nU,
                                                         Ui1, Uj1, Vi1, Vj1, bu1, bv1,
                                                         nullptr, nullptr, nullptr,
                                                         psuh, py, pxvi, n);

    scatter_kernel<<<eb, 256, 0, s1>>>(es, ee, nE);
    cudaEventRecord(g_si.evCsr, s1);

    // join: agg needs both gemm1 (main) and CSR (s1)
    cudaStreamWaitEvent(0, g_si.evCsr, 0);
    agg_kernel<<<aggBlocks, 256>>>(pxvi, psuh, py, pst1, n);

    // ---- stage 2 (BN1+ReLU fused into X load) ----
    gemm4_kernel<true><<<gemmBlocks, 256, GEMM4_SMEM>>>(py, py, n,
                                                        Ui2, Uj2, Vi2, Vj2, bu2, bv2,
                                                        pst1, gamma1, beta1,
                                                        psuh, py2, pxvi, n);
    agg_kernel<<<aggBlocks, 256>>>(pxvi, psuh, py2, pst2, n);

    // ---- final: relu(BN2(y2) + x_in @ R) ----
    final_kernel<<<finalBlocks, 256>>>(u, v, nU, R, py2, pst2, gamma2, beta2, (float*)d_out, n);
}

// round 17
// speedup vs baseline: 1.0359x; 1.0359x over previous
#include <cuda_runtime.h>
#include <cuda_fp16.h>
#include <math.h>

#define D 64
#define MAXN 100000
#define MAXE 1100000

// ---------------- static device scratch ----------------
// packed per-node record: 32 x [half2(ui_c,ui_c+1) | half2(vj_c,vj_c+1)] = 256 B
__device__ unsigned g_suh[MAXN * 64];
__device__ float g_xvi[MAXN * D];
__device__ float g_y  [MAXN * D];    // stage1 output
__device__ float g_y2 [MAXN * D];    // stage2 output
__device__ float g_stats1[2 * D];
__device__ float g_stats2[2 * D];
// CSR (edges sorted by destination)
__device__ int g_cnt[MAXN + 1];
__device__ int g_off[MAXN + 1];
__device__ int g_cur[MAXN];
__device__ int g_srcSorted[MAXE];
__device__ int g_bsum[512];

// ---------------- side stream for CSR subgraph (created before harness baseline) ----------------
namespace {
struct StreamInit {
    cudaStream_t s1;
    cudaEvent_t evRoot, evCsr;
    StreamInit() {
        cudaStreamCreateWithFlags(&s1, cudaStreamNonBlocking);
        cudaEventCreateWithFlags(&evRoot, cudaEventDisableTiming);
        cudaEventCreateWithFlags(&evCsr, cudaEventDisableTiming);
    }
};
StreamInit g_si;
}

// ================= CSR build =================
__global__ void hist_kernel(const int* __restrict__ ee, int nE)
{
    int e = blockIdx.x * blockDim.x + threadIdx.x;
    if (e < nE) atomicAdd(&g_cnt[ee[e]], 1);
}

__global__ void scan_block_kernel(int n)
{
    __shared__ int sh[256];
    int tid = threadIdx.x;
    int i = blockIdx.x * 256 + tid;
    int v = (i < n) ? g_cnt[i] : 0;
    sh[tid] = v;
    __syncthreads();
    #pragma unroll
    for (int ofs = 1; ofs < 256; ofs <<= 1) {
        int x = (tid >= ofs) ? sh[tid - ofs] : 0;
        __syncthreads();
        sh[tid] += x;
        __syncthreads();
    }
    if (i < n) g_off[i] = sh[tid] - v;
    if (tid == 255) g_bsum[blockIdx.x] = sh[255];
}

__global__ void scan_add_kernel(int n)
{
    __shared__ int s_prefix;
    const int bid = blockIdx.x;
    if (bid == 0 && threadIdx.x < 128) {
        g_stats1[threadIdx.x] = 0.f;
        g_stats2[threadIdx.x] = 0.f;
    }
    if (threadIdx.x < 32) {
        int s = 0;
        for (int i = threadIdx.x; i < bid; i += 32) s += g_bsum[i];
        #pragma unroll
        for (int o = 16; o; o >>= 1) s += __shfl_down_sync(0xffffffffu, s, o);
        if (threadIdx.x == 0) s_prefix = s;
    }
    __syncthreads();
    int i = bid * 256 + threadIdx.x;
    if (i < n) {
        int o = g_off[i] + s_prefix;
        g_off[i] = o;
        g_cur[i] = o;
        if (i == n - 1) g_off[n] = o + g_cnt[i];
    }
}

__global__ void scatter_kernel(const int* __restrict__ es, const int* __restrict__ ee, int nE)
{
    int e = blockIdx.x * blockDim.x + threadIdx.x;
    if (e < nE) {
        int d = ee[e];
        int p = atomicAdd(&g_cur[d], 1);
        g_srcSorted[p] = es[e];
    }
}

// ================= tf32 mma helpers =================
__device__ __forceinline__ unsigned f2tf32(float x)
{
    unsigned r;
    asm("cvt.rna.tf32.f32 %0, %1;" : "=r"(r) : "f"(x));
    return r;
}

__device__ __forceinline__ void mma_tf32(float* d, unsigned a0, unsigned a1,
                                         unsigned a2, unsigned a3,
                                         unsigned b0, unsigned b1)
{
    asm volatile(
        "mma.sync.aligned.m16n8k8.row.col.f32.tf32.tf32.f32 "
        "{%0,%1,%2,%3}, {%4,%5,%6,%7}, {%8,%9}, {%0,%1,%2,%3};"
        : "+f"(d[0]), "+f"(d[1]), "+f"(d[2]), "+f"(d[3])
        : "r"(a0), "r"(a1), "r"(a2), "r"(a3), "r"(b0), "r"(b1));
}

__device__ __forceinline__ unsigned pack_h2(float a, float b)
{
    __half2 h = __floats2half2_rn(a, b);
    return *reinterpret_cast<unsigned*>(&h);
}

// ================= fused 4-matrix GEMM via tf32 tensor cores (persistent) =================
// W staged once per persistent block; As holds a FULL 128-row tile (one sync pair per tile).
#define WS_STRIDE 264
#define AS_STRIDE 68
#define GEMM4_SMEM ((64*WS_STRIDE + 128*AS_STRIDE)*4)

template<bool BN>
__global__ void __launch_bounds__(256, 2)
gemm4_kernel(const float* __restrict__ X, const float* __restrict__ Xv, int nU,
             const float* __restrict__ Ui, const float* __restrict__ Uj,
             const float* __restrict__ Vi, const float* __restrict__ Vj,
             const float* __restrict__ bu, const float* __restrict__ bv,
             const float* __restrict__ stats, const float* __restrict__ gamma,
             const float* __restrict__ beta,
             unsigned* __restrict__ suh, float* __restrict__ y,
             float* __restrict__ xvi,
             int n)
{
    extern __shared__ float smem[];
    unsigned* Ws = (unsigned*)smem;                       // [64][264] tf32 bits
    unsigned* As = (unsigned*)(smem + 64 * WS_STRIDE);    // [128][68] tf32 bits
    __shared__ float s_scale[64], s_shift[64];
    const int tid = threadIdx.x;

    if (BN) {
        if (tid < 64) {
            float fn = 1.f / (float)n;
            float mean = stats[tid] * fn;
            float var  = stats[64 + tid] * fn - mean * mean;
            float sc = gamma[tid] * rsqrtf(var + 1e-3f);
            s_scale[tid] = sc;
            s_shift[tid] = beta[tid] - mean * sc;
        }
        __syncthreads();
    }

    // stage W once per (persistent) block
    {
        const float* mats[4] = {Ui, Uj, Vi, Vj};
        #pragma unroll
        for (int m = 0; m < 4; m++) {
            const float4* src = (const float4*)mats[m];
            for (int i = tid; i < 1024; i += 256) {
                int k = i >> 4, j4 = i & 15;
                float4 w = src[i];
                uint4 p;
                p.x = f2tf32(w.x); p.y = f2tf32(w.y);
                p.z = f2tf32(w.z); p.w = f2tf32(w.w);
                *(uint4*)(Ws + k * WS_STRIDE + m * 64 + j4 * 4) = p;
            }
        }
    }

    const int warp = tid >> 5;
    const int lane = tid & 31;
    const int g = lane >> 2;
    const int t = lane & 3;
    const int nbase = warp * 8;
    const int c = nbase + 2 * t;
    float2 bu2 = *(const float2*)(bu + c);
    float2 bv2 = *(const float2*)(bv + c);

    const int nTiles = (n + 127) / 128;

    for (int tile = blockIdx.x; tile < nTiles; tile += gridDim.x) {
        const int rowBase0 = tile * 128;

        __syncthreads();   // protect As from previous tile's readers
        // stage full 128-row tile
        for (int i = tid; i < 2048; i += 256) {
            int r = i >> 4, c4 = i & 15;
            int row = rowBase0 + r;
            float4 v = make_float4(0.f, 0.f, 0.f, 0.f);
            if (row < n) {
                const float4* src = (row < nU) ? ((const float4*)X) + (size_t)row * 16
                                               : ((const float4*)Xv) + (size_t)(row - nU) * 16;
                v = src[c4];
            }
            if (BN) {
                int cc = c4 * 4;
                v.x = fmaxf(v.x * s_scale[cc+0] + s_shift[cc+0], 0.f);
                v.y = fmaxf(v.y * s_scale[cc+1] + s_shift[cc+1], 0.f);
                v.z = fmaxf(v.z * s_scale[cc+2] + s_shift[cc+2], 0.f);
                v.w = fmaxf(v.w * s_scale[cc+3] + s_shift[cc+3], 0.f);
            }
            uint4 p;
            p.x = f2tf32(v.x); p.y = f2tf32(v.y);
            p.z = f2tf32(v.z); p.w = f2tf32(v.w);
            *(uint4*)(As + r * AS_STRIDE + c4 * 4) = p;
        }
        __syncthreads();

        #pragma unroll 1
        for (int st = 0; st < 2; st++) {
            const int rowBase = rowBase0 + st * 64;
            if (rowBase >= n) break;
            const unsigned* Ast = As + st * 64 * AS_STRIDE;

            float acc[4][4][4];   // [mtile][matrix][c0..c3]
            #pragma unroll
            for (int mt = 0; mt < 4; mt++)
                #pragma unroll
                for (int nt = 0; nt < 4; nt++)
                    #pragma unroll
                    for (int cc = 0; cc < 4; cc++) acc[mt][nt][cc] = 0.f;

            #pragma unroll
            for (int k0 = 0; k0 < 64; k0 += 8) {
                unsigned b[4][2];
                #pragma unroll
                for (int nt = 0; nt < 4; nt++) {
                    int cb = nt * 64 + nbase;
                    b[nt][0] = Ws[(k0 + t)     * WS_STRIDE + cb + g];
                    b[nt][1] = Ws[(k0 + t + 4) * WS_STRIDE + cb + g];
                }
                #pragma unroll
                for (int mt = 0; mt < 4; mt++) {
                    int r0 = mt * 16;
                    unsigned a0 = Ast[(r0 + g)     * AS_STRIDE + k0 + t];
                    unsigned a1 = Ast[(r0 + g + 8) * AS_STRIDE + k0 + t];
                    unsigned a2 = Ast[(r0 + g)     * AS_STRIDE + k0 + t + 4];
                    unsigned a3 = Ast[(r0 + g + 8) * AS_STRIDE + k0 + t + 4];
                    #pragma unroll
                    for (int nt = 0; nt < 4; nt++)
                        mma_tf32(acc[mt][nt], a0, a1, a2, a3, b[nt][0], b[nt][1]);
                }
            }

            #pragma unroll
            for (int mt = 0; mt < 4; mt++) {
                #pragma unroll
                for (int h = 0; h < 2; h++) {
                    int row = rowBase + mt * 16 + g + 8 * h;
                    if (row < n) {
                        float u0  = acc[mt][0][2*h],   u1  = acc[mt][0][2*h+1];
                        float j0  = acc[mt][1][2*h] + bu2.x, j1 = acc[mt][1][2*h+1] + bu2.y;
                        float vi0 = acc[mt][2][2*h],   vi1 = acc[mt][2][2*h+1];
                        float vj0 = acc[mt][3][2*h] + bv2.x, vj1 = acc[mt][3][2*h+1] + bv2.y;
                        *(float2*)(y   + (size_t)row * 64 + c) = make_float2(j0, j1);
                        *(float2*)(xvi + (size_t)row * 64 + c) = make_float2(vi0, vi1);
                        uint2 pk;
                        pk.x = pack_h2(u0, u1);    // half2(ui_c, ui_c+1)
                        pk.y = pack_h2(vj0, vj1);  // half2(vj_c, vj_c+1)
                        *(uint2*)(suh + (size_t)row * 64 + c) = pk;
                    }
                }
            }
        }
    }
}

// ================= per-node aggregation: f16x2-vectorized gate, 4 nodes/warp =================
__device__ __forceinline__ __half2 u2h(unsigned u)
{
    return *reinterpret_cast<__half2*>(&u);
}

__device__ __forceinline__ __half2 tanh_h2(__half2 x)
{
    unsigned xi = *reinterpret_cast<unsigned*>(&x);
    unsigned r;
    asm("tanh.approx.f16x2 %0, %1;" : "=r"(r) : "r"(xi));
    return *reinterpret_cast<__half2*>(&r);
}

__device__ __forceinline__ void edge_acc(float4& acc, __half2 viha, __half2 vihb,
                                         __half2 h05, uint4 pk)
{
    __half2 ua = u2h(pk.x), va = u2h(pk.y);
    __half2 ub = u2h(pk.z), vb = u2h(pk.w);
    __half2 xa = __hfma2(va, h05, viha);
    __half2 xb = __hfma2(vb, h05, vihb);
    __half2 ga = __hfma2(tanh_h2(xa), h05, h05);
    __half2 gb = __hfma2(tanh_h2(xb), h05, h05);
    __half2 ma = __hmul2(ua, ga);
    __half2 mb = __hmul2(ub, gb);
    float2 fa = __half22float2(ma);
    float2 fb = __half22float2(mb);
    acc.x += fa.x; acc.y += fa.y; acc.z += fb.x; acc.w += fb.y;
}

__global__ void agg_kernel(const float* __restrict__ xvi, const unsigned* __restrict__ suh,
                           float* __restrict__ y, float* __restrict__ stats, int n)
{
    __shared__ float s_sum[64], s_sum2[64];
    const int tid = threadIdx.x;
    if (tid < 64) { s_sum[tid] = 0.f; s_sum2[tid] = 0.f; }
    __syncthreads();

    const int warp = tid >> 5;
    const int lane = tid & 31;
    const int half = lane >> 4;
    const int l4   = lane & 15;
    const int nodeBase = blockIdx.x * 32 + warp * 4;
    const __half2 h05 = __float2half2_rn(0.5f);

    float4 st1 = make_float4(0.f, 0.f, 0.f, 0.f);
    float4 st2 = make_float4(0.f, 0.f, 0.f, 0.f);

    #pragma unroll 1
    for (int q = 0; q < 4; q++) {
        const int node = nodeBase + q;
        if (node >= n) break;

        float4 vi = ((const float4*)(xvi + (size_t)node * 64))[l4];
        float4 base = ((const float4*)(y + (size_t)node * 64))[l4];
        __half2 viha = __floats2half2_rn(0.5f * vi.x, 0.5f * vi.y);
        __half2 vihb = __floats2half2_rn(0.5f * vi.z, 0.5f * vi.w);
        float4 acc = make_float4(0.f, 0.f, 0.f, 0.f);
        const int p0 = g_off[node];
        const int p1 = g_off[node + 1];

        int pp = p0 + half;
        for (; pp + 6 < p1; pp += 8) {
            int b0 = __ldg(g_srcSorted + pp);
            int b1 = __ldg(g_srcSorted + pp + 2);
            int b2 = __ldg(g_srcSorted + pp + 4);
            int b3 = __ldg(g_srcSorted + pp + 6);
            uint4 k0 = __ldg((const uint4*)(suh + (size_t)b0 * 64) + l4);
            uint4 k1 = __ldg((const uint4*)(suh + (size_t)b1 * 64) + l4);
            uint4 k2 = __ldg((const uint4*)(suh + (size_t)b2 * 64) + l4);
            uint4 k3 = __ldg((const uint4*)(suh + (size_t)b3 * 64) + l4);
            edge_acc(acc, viha, vihb, h05, k0);
            edge_acc(acc, viha, vihb, h05, k1);
            edge_acc(acc, viha, vihb, h05, k2);
            edge_acc(acc, viha, vihb, h05, k3);
        }
        for (; pp + 2 < p1; pp += 4) {
            int b0 = __ldg(g_srcSorted + pp);
            int b1 = __ldg(g_srcSorted + pp + 2);
            uint4 k0 = __ldg((const uint4*)(suh + (size_t)b0 * 64) + l4);
            uint4 k1 = __ldg((const uint4*)(suh + (size_t)b1 * 64) + l4);
            edge_acc(acc, viha, vihb, h05, k0);
            edge_acc(acc, viha, vihb, h05, k1);
        }
        for (; pp < p1; pp += 2) {
            int b = __ldg(g_srcSorted + pp);
            uint4 k = __ldg((const uint4*)(suh + (size_t)b * 64) + l4);
            edge_acc(acc, viha, vihb, h05, k);
        }

        acc.x += __shfl_xor_sync(0xffffffffu, acc.x, 16);
        acc.y += __shfl_xor_sync(0xffffffffu, acc.y, 16);
        acc.z += __shfl_xor_sync(0xffffffffu, acc.z, 16);
        acc.w += __shfl_xor_sync(0xffffffffu, acc.w, 16);

        if (half == 0) {
            acc.x += base.x; acc.y += base.y; acc.z += base.z; acc.w += base.w;
            ((float4*)(y + (size_t)node * 64))[l4] = acc;
            st1.x += acc.x; st1.y += acc.y; st1.z += acc.z; st1.w += acc.w;
            st2.x += acc.x * acc.x; st2.y += acc.y * acc.y;
            st2.z += acc.z * acc.z; st2.w += acc.w * acc.w;
        }
    }

    if (half == 0) {
        int cc = l4 * 4;
        atomicAdd(&s_sum[cc + 0], st1.x);  atomicAdd(&s_sum2[cc + 0], st2.x);
        atomicAdd(&s_sum[cc + 1], st1.y);  atomicAdd(&s_sum2[cc + 1], st2.y);
        atomicAdd(&s_sum[cc + 2], st1.z);  atomicAdd(&s_sum2[cc + 2], st2.z);
        atomicAdd(&s_sum[cc + 3], st1.w);  atomicAdd(&s_sum2[cc + 3], st2.w);
    }
    __syncthreads();
    if (tid < 64) {
        atomicAdd(stats + tid,      s_sum[tid]);
        atomicAdd(stats + 64 + tid, s_sum2[tid]);
    }
}

// ================= final: out = relu( BN2(y2) + x_in @ R ) via tf32 MMA =================
#define RS_STRIDE 72
#define FAS_STRIDE 68

__global__ void __launch_bounds__(256)
final_kernel(const float* __restrict__ Xu, const float* __restrict__ Xv, int nU,
             const float* __restrict__ R,
             const float* __restrict__ y2, const float* __restrict__ stats,
             const float* __restrict__ gamma, const float* __restrict__ beta,
             float* __restrict__ out, int n)
{
    __shared__ unsigned Rs[64 * RS_STRIDE];
    __shared__ unsigned As[64 * FAS_STRIDE];
    const int tid = threadIdx.x;
    const int rowBase = blockIdx.x * 64;

    for (int i = tid; i < 1024; i += 256) {
        int k = i >> 4, j4 = i & 15;
        float4 w = ((const float4*)R)[i];
        uint4 p;
        p.x = f2tf32(w.x); p.y = f2tf32(w.y);
        p.z = f2tf32(w.z); p.w = f2tf32(w.w);
        *(uint4*)(Rs + k * RS_STRIDE + j4 * 4) = p;
    }
    for (int i = tid; i < 1024; i += 256) {
        int r = i >> 4, c4 = i & 15;
        int row = rowBase + r;
        float4 v = make_float4(0.f, 0.f, 0.f, 0.f);
        if (row < n) {
            const float4* src = (row < nU) ? ((const float4*)Xu) + (size_t)row * 16
                                           : ((const float4*)Xv) + (size_t)(row - nU) * 16;
            v = src[c4];
        }
        uint4 p;
        p.x = f2tf32(v.x); p.y = f2tf32(v.y);
        p.z = f2tf32(v.z); p.w = f2tf32(v.w);
        *(uint4*)(As + r * FAS_STRIDE + c4 * 4) = p;
    }
    __syncthreads();

    const int warp = tid >> 5;
    const int lane = tid & 31;
    const int g = lane >> 2;
    const int t = lane & 3;
    const int cb = warp * 8;

    float acc[4][4];
    #pragma unroll
    for (int mt = 0; mt < 4; mt++)
        #pragma unroll
        for (int cc = 0; cc < 4; cc++) acc[mt][cc] = 0.f;

    #pragma unroll
    for (int k0 = 0; k0 < 64; k0 += 8) {
        unsigned b0 = Rs[(k0 + t)     * RS_STRIDE + cb + g];
        unsigned b1 = Rs[(k0 + t + 4) * RS_STRIDE + cb + g];
        #pragma unroll
        for (int mt = 0; mt < 4; mt++) {
            int r0 = mt * 16;
            unsigned a0 = As[(r0 + g)     * FAS_STRIDE + k0 + t];
            unsigned a1 = As[(r0 + g + 8) * FAS_STRIDE + k0 + t];
            unsigned a2 = As[(r0 + g)     * FAS_STRIDE + k0 + t + 4];
            unsigned a3 = As[(r0 + g + 8) * FAS_STRIDE + k0 + t + 4];
            mma_tf32(acc[mt], a0, a1, a2, a3, b0, b1);
        }
    }

    const int c = cb + 2 * t;
    float fn = 1.f / (float)n;
    float scale[2], shift[2];
    #pragma unroll
    for (int j = 0; j < 2; j++) {
        int cc = c + j;
        float mean = stats[cc] * fn;
        float var  = stats[64 + cc] * fn - mean * mean;
        float sc = gamma[cc] * rsqrtf(var + 1e-3f);
        scale[j] = sc;
        shift[j] = beta[cc] - mean * sc;
    }

    #pragma unroll
    for (int mt = 0; mt < 4; mt++) {
        #pragma unroll
        for (int h = 0; h < 2; h++) {
            int row = rowBase + mt * 16 + g + 8 * h;
            if (row < n) {
                float2 yv = *(const float2*)(y2 + (size_t)row * 64 + c);
                float o0 = acc[mt][2*h]   + yv.x * scale[0] + shift[0];
                float o1 = acc[mt][2*h+1] + yv.y * scale[1] + shift[1];
                float2 ov;
                ov.x = o0 > 0.f ? o0 : 0.f;
                ov.y = o1 > 0.f ? o1 : 0.f;
                *(float2*)(out + (size_t)row * 64 + c) = ov;
            }
        }
    }
}

// ================= host =================
extern "C" void kernel_launch(void* const* d_in, const int* in_sizes, int n_in,
                              void* d_out, int out_size)
{
    const float* u   = (const float*)d_in[0];
    const float* v   = (const float*)d_in[1];
    const int*   es  = (const int*)  d_in[2];
    const int*   ee  = (const int*)  d_in[3];
    const float* Ui1 = (const float*)d_in[4];
    const float* Uj1 = (const float*)d_in[5];
    const float* Vi1 = (const float*)d_in[6];
    const float* Vj1 = (const float*)d_in[7];
    const float* bu1 = (const float*)d_in[8];
    const float* bv1 = (const float*)d_in[9];
    const float* Ui2 = (const float*)d_in[10];
    const float* Uj2 = (const float*)d_in[11];
    const float* Vi2 = (const float*)d_in[12];
    const float* Vj2 = (const float*)d_in[13];
    const float* bu2 = (const float*)d_in[14];
    const float* bv2 = (const float*)d_in[15];
    const float* R   = (const float*)d_in[16];
    const float* gamma1 = (const float*)d_in[17];
    const float* beta1  = (const float*)d_in[18];
    const float* gamma2 = (const float*)d_in[19];
    const float* beta2  = (const float*)d_in[20];

    const int nU = in_sizes[0] / 64;
    const int nV = in_sizes[1] / 64;
    const int n  = nU + nV;
    const int nE = in_sizes[2];

    float *pxvi, *py, *py2, *pst1, *pst2;
    unsigned *psuh;
    int *pcnt;
    cudaGetSymbolAddress((void**)&psuh, g_suh);
    cudaGetSymbolAddress((void**)&pxvi, g_xvi);
    cudaGetSymbolAddress((void**)&py,   g_y);
    cudaGetSymbolAddress((void**)&py2,  g_y2);
    cudaGetSymbolAddress((void**)&pst1, g_stats1);
    cudaGetSymbolAddress((void**)&pst2, g_stats2);
    cudaGetSymbolAddress((void**)&pcnt, g_cnt);

    cudaFuncSetAttribute(gemm4_kernel<false>, cudaFuncAttributeMaxDynamicSharedMemorySize, GEMM4_SMEM);
    cudaFuncSetAttribute(gemm4_kernel<true>,  cudaFuncAttributeMaxDynamicSharedMemorySize, GEMM4_SMEM);

    const int eb = (nE + 255) / 256;
    const int nb = (n + 255) / 256;
    const int nTiles = (n + 127) / 128;
    const int gemmBlocks  = nTiles < 296 ? nTiles : 296;
    const int finalBlocks = (n + 63) / 64;
    const int aggBlocks   = (n + 31) / 32;

    cudaStream_t s1 = g_si.s1;

    // fork: CSR subgraph on side stream (depends only on es/ee)
    cudaEventRecord(g_si.evRoot, 0);
    cudaStreamWaitEvent(s1, g_si.evRoot, 0);

    cudaMemsetAsync(pcnt, 0, (MAXN + 1) * sizeof(int), s1);
    hist_kernel<<<eb, 256, 0, s1>>>(ee, nE);
    scan_block_kernel<<<nb, 256, 0, s1>>>(n);
    scan_add_kernel<<<nb, 256, 0, s1>>>(n);

    // ---- stage 1 GEMM on main stream (concurrent with CSR build) ----
    gemm4_kernel<false><<<gemmBlocks, 256, GEMM4_SMEM>>>(u, v, nU,
                                                         Ui1, Uj1, Vi1, Vj1, bu1, bv1,
                                                         nullptr, nullptr, nullptr,
                                                         psuh, py, pxvi, n);

    scatter_kernel<<<eb, 256, 0, s1>>>(es, ee, nE);
    cudaEventRecord(g_si.evCsr, s1);

    // join: agg needs both gemm1 (main) and CSR (s1)
    cudaStreamWaitEvent(0, g_si.evCsr, 0);
    agg_kernel<<<aggBlocks, 256>>>(pxvi, psuh, py, pst1, n);

    // ---- stage 2 (BN1+ReLU fused into X load) ----
    gemm4_kernel<true><<<gemmBlocks, 256, GEMM4_SMEM>>>(py, py, n,
                                                        Ui2, Uj2, Vi2, Vj2, bu2, bv2,
                                                        pst1, gamma1, beta1,
                                                        psuh, py2, pxvi, n);
    agg_kernel<<<aggBlocks, 256>>>(pxvi, psuh, py2, pst2, n);

    // ---- final: relu(BN2(y2) + x_in @ R) ----
    final_kernel<<<finalBlocks, 256>>>(u, v, nU, R, py2, pst2, gamma2, beta2, (float*)d_out, n);
}